// round 3
// baseline (speedup 1.0000x reference)
#include <cuda_runtime.h>
#include <math_constants.h>

// Problem constants
#define S_LEN 1024
#define B_SZ  8
#define H_DIM 1024
#define NHEAD 16
#define HDIM  64
#define M_ROWS (B_SZ * S_LEN)   // 8192

// Scratch for projected Q/K/V, laid out as [B*S, H] with m = b*S_LEN + s.
// (__device__ globals: allowed; cudaMalloc is not.)
__device__ float g_QL[(size_t)M_ROWS * H_DIM];
__device__ float g_KL[(size_t)M_ROWS * H_DIM];
__device__ float g_VL[(size_t)M_ROWS * H_DIM];

// ---------------------------------------------------------------------------
// Projection GEMM: Y[m][n] = sum_k X[(s*B+b)][k] * W[n][k] + bias[n]
//   X is [S, B, H] (seq-first), m = b*S + s (batch-first row index).
//   128x128 block tile, BK=16, 256 threads, 8x8 per thread.
// ---------------------------------------------------------------------------
__global__ __launch_bounds__(256) void proj_kernel(
    const float* __restrict__ X, const float* __restrict__ W,
    const float* __restrict__ bias, int which)
{
    float* out = (which == 0) ? g_QL : ((which == 1) ? g_KL : g_VL);

    const int BM = 128, BN = 128, BK = 16;
    __shared__ float As[BK][BM + 4];   // [k][m], padded (row=132 floats, 16B-aligned)
    __shared__ float Bs[BK][BN + 4];   // [k][n]

    const int m0 = blockIdx.y * BM;
    const int n0 = blockIdx.x * BN;
    const int tid = threadIdx.x;
    const int tx = tid & 15;           // 0..15 -> n
    const int ty = tid >> 4;           // 0..15 -> m

    float acc[8][8];
    #pragma unroll
    for (int i = 0; i < 8; i++)
        #pragma unroll
        for (int j = 0; j < 8; j++) acc[i][j] = 0.0f;

    for (int k0 = 0; k0 < H_DIM; k0 += BK) {
        // Load A tile: 128 rows x 16 cols = 512 float4, 2 per thread
        #pragma unroll
        for (int l = 0; l < 2; l++) {
            int f  = l * 256 + tid;
            int r  = f >> 2;           // 0..127
            int c4 = f & 3;            // 0..3
            int m  = m0 + r;
            int b  = m >> 10;          // /S_LEN
            int s  = m & 1023;
            const float4 v = *reinterpret_cast<const float4*>(
                X + ((size_t)(s * B_SZ + b)) * H_DIM + k0 + c4 * 4);
            As[c4 * 4 + 0][r] = v.x;
            As[c4 * 4 + 1][r] = v.y;
            As[c4 * 4 + 2][r] = v.z;
            As[c4 * 4 + 3][r] = v.w;
        }
        // Load B tile from W[n][k]: 128 rows x 16 cols
        #pragma unroll
        for (int l = 0; l < 2; l++) {
            int f  = l * 256 + tid;
            int r  = f >> 2;
            int c4 = f & 3;
            const float4 v = *reinterpret_cast<const float4*>(
                W + (size_t)(n0 + r) * H_DIM + k0 + c4 * 4);
            Bs[c4 * 4 + 0][r] = v.x;
            Bs[c4 * 4 + 1][r] = v.y;
            Bs[c4 * 4 + 2][r] = v.z;
            Bs[c4 * 4 + 3][r] = v.w;
        }
        __syncthreads();

        #pragma unroll
        for (int kk = 0; kk < BK; kk++) {
            float4 a0 = *reinterpret_cast<const float4*>(&As[kk][ty * 8]);
            float4 a1 = *reinterpret_cast<const float4*>(&As[kk][ty * 8 + 4]);
            float4 b0 = *reinterpret_cast<const float4*>(&Bs[kk][tx * 8]);
            float4 b1 = *reinterpret_cast<const float4*>(&Bs[kk][tx * 8 + 4]);
            float a[8] = {a0.x, a0.y, a0.z, a0.w, a1.x, a1.y, a1.z, a1.w};
            float bb[8] = {b0.x, b0.y, b0.z, b0.w, b1.x, b1.y, b1.z, b1.w};
            #pragma unroll
            for (int i = 0; i < 8; i++)
                #pragma unroll
                for (int j = 0; j < 8; j++)
                    acc[i][j] += a[i] * bb[j];
        }
        __syncthreads();
    }

    // Epilogue: += bias, write [m][n] coalesced
    #pragma unroll
    for (int i = 0; i < 8; i++) {
        int m = m0 + ty * 8 + i;
        size_t rowo = (size_t)m * H_DIM;
        #pragma unroll
        for (int j = 0; j < 8; j++) {
            int n = n0 + tx * 8 + j;
            out[rowo + n] = acc[i][j] + bias[n];
        }
    }
}

// ---------------------------------------------------------------------------
// Scores: for each (b,h): Sc[q][k] = (Q_bh[q] . K_bh[k]) / 8 + mask_add[b][k]
//   Raw (pre-softmax) scores written straight into the attn_weights output
//   region (used as scratch; softmax normalizes in place afterwards).
//   GEMM: M=N=1024, K=64. 128x128 block, BK=16.
// ---------------------------------------------------------------------------
__global__ __launch_bounds__(256) void scores_kernel(
    const int* __restrict__ mask, float* __restrict__ out_w)
{
    const int bh = blockIdx.z;
    const int b = bh >> 4;      // /NHEAD
    const int h = bh & 15;
    const float* Qb = g_QL + (size_t)b * S_LEN * H_DIM + h * HDIM;
    const float* Kb = g_KL + (size_t)b * S_LEN * H_DIM + h * HDIM;

    const int BM = 128, BN = 128, BK = 16;
    __shared__ float As[BK][BM + 4];
    __shared__ float Bs[BK][BN + 4];

    const int q0 = blockIdx.y * BM;
    const int n0 = blockIdx.x * BN;
    const int tid = threadIdx.x;
    const int tx = tid & 15, ty = tid >> 4;

    float acc[8][8];
    #pragma unroll
    for (int i = 0; i < 8; i++)
        #pragma unroll
        for (int j = 0; j < 8; j++) acc[i][j] = 0.0f;

    for (int k0 = 0; k0 < HDIM; k0 += BK) {
        #pragma unroll
        for (int l = 0; l < 2; l++) {
            int f = l * 256 + tid;
            int r = f >> 2, c4 = f & 3;
            const float4 v = *reinterpret_cast<const float4*>(
                Qb + (size_t)(q0 + r) * H_DIM + k0 + c4 * 4);
            As[c4 * 4 + 0][r] = v.x; As[c4 * 4 + 1][r] = v.y;
            As[c4 * 4 + 2][r] = v.z; As[c4 * 4 + 3][r] = v.w;
        }
        #pragma unroll
        for (int l = 0; l < 2; l++) {
            int f = l * 256 + tid;
            int r = f >> 2, c4 = f & 3;
            const float4 v = *reinterpret_cast<const float4*>(
                Kb + (size_t)(n0 + r) * H_DIM + k0 + c4 * 4);
            Bs[c4 * 4 + 0][r] = v.x; Bs[c4 * 4 + 1][r] = v.y;
            Bs[c4 * 4 + 2][r] = v.z; Bs[c4 * 4 + 3][r] = v.w;
        }
        __syncthreads();

        #pragma unroll
        for (int kk = 0; kk < BK; kk++) {
            float4 a0 = *reinterpret_cast<const float4*>(&As[kk][ty * 8]);
            float4 a1 = *reinterpret_cast<const float4*>(&As[kk][ty * 8 + 4]);
            float4 b0 = *reinterpret_cast<const float4*>(&Bs[kk][tx * 8]);
            float4 b1 = *reinterpret_cast<const float4*>(&Bs[kk][tx * 8 + 4]);
            float a[8] = {a0.x, a0.y, a0.z, a0.w, a1.x, a1.y, a1.z, a1.w};
            float bb[8] = {b0.x, b0.y, b0.z, b0.w, b1.x, b1.y, b1.z, b1.w};
            #pragma unroll
            for (int i = 0; i < 8; i++)
                #pragma unroll
                for (int j = 0; j < 8; j++)
                    acc[i][j] += a[i] * bb[j];
        }
        __syncthreads();
    }

    // mask add per output column (key position)
    float madd[8];
    #pragma unroll
    for (int j = 0; j < 8; j++) {
        int n = n0 + tx * 8 + j;
        madd[j] = (mask[b * S_LEN + n] != 0) ? -1000000.0f : 0.0f;
    }

    const float scale = 0.125f;   // 1/sqrt(64)
    #pragma unroll
    for (int i = 0; i < 8; i++) {
        int q = q0 + ty * 8 + i;
        size_t rowo = ((size_t)bh * S_LEN + q) * S_LEN;
        #pragma unroll
        for (int j = 0; j < 8; j++) {
            int n = n0 + tx * 8 + j;
            out_w[rowo + n] = acc[i][j] * scale + madd[j];
        }
    }
}

// ---------------------------------------------------------------------------
// Softmax in place over last dim (1024). One warp per row, all in registers.
// ---------------------------------------------------------------------------
__global__ __launch_bounds__(256) void softmax_kernel(float* __restrict__ w)
{
    const int gwarp = (int)((blockIdx.x * blockDim.x + threadIdx.x) >> 5);
    const int lane = threadIdx.x & 31;
    // total rows = B*NH*S = 131072; grid sized exactly
    float* row = w + (size_t)gwarp * S_LEN;

    float v[32];
    float mx = -CUDART_INF_F;
    #pragma unroll
    for (int i = 0; i < 32; i++) {
        v[i] = row[i * 32 + lane];
        mx = fmaxf(mx, v[i]);
    }
    #pragma unroll
    for (int o = 16; o > 0; o >>= 1)
        mx = fmaxf(mx, __shfl_xor_sync(0xffffffffu, mx, o));

    float sum = 0.0f;
    #pragma unroll
    for (int i = 0; i < 32; i++) {
        v[i] = __expf(v[i] - mx);
        sum += v[i];
    }
    #pragma unroll
    for (int o = 16; o > 0; o >>= 1)
        sum += __shfl_xor_sync(0xffffffffu, sum, o);

    const float inv = 1.0f / sum;
    #pragma unroll
    for (int i = 0; i < 32; i++)
        row[i * 32 + lane] = v[i] * inv;
}

// ---------------------------------------------------------------------------
// Context: for each (b,h): C[q][d] = sum_k P[q][k] * V_bh[k][d]
//   M=1024, N=64, K=1024. 128x64 block, BK=16, 8x4 per thread.
//   Output written in final [S, B, H] layout.
// ---------------------------------------------------------------------------
__global__ __launch_bounds__(256) void ctx_kernel(
    const float* __restrict__ w, float* __restrict__ out_ctx)
{
    const int bh = blockIdx.z;
    const int b = bh >> 4;
    const int h = bh & 15;
    const float* P  = w + (size_t)bh * S_LEN * S_LEN;
    const float* Vb = g_VL + (size_t)b * S_LEN * H_DIM + h * HDIM;

    const int BM = 128, BK = 16;
    __shared__ float As[BK][BM + 4];   // P^T tile
    __shared__ float Bs[BK][64];       // V tile [k][d]

    const int q0 = blockIdx.y * BM;
    const int tid = threadIdx.x;
    const int tx = tid & 15;   // -> d (x4)
    const int ty = tid >> 4;   // -> q (x8)

    float acc[8][4];
    #pragma unroll
    for (int i = 0; i < 8; i++)
        #pragma unroll
        for (int j = 0; j < 4; j++) acc[i][j] = 0.0f;

    for (int k0 = 0; k0 < S_LEN; k0 += BK) {
        // A tile: 128 rows x 16 cols of P
        #pragma unroll
        for (int l = 0; l < 2; l++) {
            int f = l * 256 + tid;
            int r = f >> 2, c4 = f & 3;
            const float4 v = *reinterpret_cast<const float4*>(
                P + (size_t)(q0 + r) * S_LEN + k0 + c4 * 4);
            As[c4 * 4 + 0][r] = v.x; As[c4 * 4 + 1][r] = v.y;
            As[c4 * 4 + 2][r] = v.z; As[c4 * 4 + 3][r] = v.w;
        }
        // B tile: 16 rows x 64 cols of V, one float4 per thread
        {
            int r = tid >> 4, c4 = tid & 15;
            const float4 v = *reinterpret_cast<const float4*>(
                Vb + (size_t)(k0 + r) * H_DIM + c4 * 4);
            *reinterpret_cast<float4*>(&Bs[r][c4 * 4]) = v;
        }
        __syncthreads();

        #pragma unroll
        for (int kk = 0; kk < BK; kk++) {
            float4 a0 = *reinterpret_cast<const float4*>(&As[kk][ty * 8]);
            float4 a1 = *reinterpret_cast<const float4*>(&As[kk][ty * 8 + 4]);
            float4 b0 = *reinterpret_cast<const float4*>(&Bs[kk][tx * 4]);
            float a[8] = {a0.x, a0.y, a0.z, a0.w, a1.x, a1.y, a1.z, a1.w};
            float bb[4] = {b0.x, b0.y, b0.z, b0.w};
            #pragma unroll
            for (int i = 0; i < 8; i++)
                #pragma unroll
                for (int j = 0; j < 4; j++)
                    acc[i][j] += a[i] * bb[j];
        }
        __syncthreads();
    }

    // Write ctx in [S, B, H] layout: out[(s*B + b)*H + h*64 + d]
    #pragma unroll
    for (int i = 0; i < 8; i++) {
        int s = q0 + ty * 8 + i;
        size_t base = ((size_t)s * B_SZ + b) * H_DIM + h * HDIM;
        #pragma unroll
        for (int j = 0; j < 4; j++) {
            int d = tx * 4 + j;
            out_ctx[base + d] = acc[i][j];
        }
    }
}

// ---------------------------------------------------------------------------
// Launch
// ---------------------------------------------------------------------------
extern "C" void kernel_launch(void* const* d_in, const int* in_sizes, int n_in,
                              void* d_out, int out_size)
{
    const float* q_states = (const float*)d_in[0];
    const float* k_states = (const float*)d_in[1];
    const float* v_states = (const float*)d_in[2];
    const int*   mask     = (const int*)  d_in[3];  // bool promoted to int32
    const float* Wq = (const float*)d_in[4];
    const float* bq = (const float*)d_in[5];
    const float* Wk = (const float*)d_in[6];
    const float* bk = (const float*)d_in[7];
    const float* Wv = (const float*)d_in[8];
    const float* bv = (const float*)d_in[9];

    float* out_ctx = (float*)d_out;                       // [S, B, H]
    float* out_w   = out_ctx + (size_t)S_LEN * B_SZ * H_DIM;  // [B, NH, S, S]

    dim3 pg(H_DIM / 128, M_ROWS / 128);      // (8, 64)
    proj_kernel<<<pg, 256>>>(q_states, Wq, bq, 0);
    proj_kernel<<<pg, 256>>>(k_states, Wk, bk, 1);
    proj_kernel<<<pg, 256>>>(v_states, Wv, bv, 2);

    dim3 sg(S_LEN / 128, S_LEN / 128, B_SZ * NHEAD);  // (8, 8, 128)
    scores_kernel<<<sg, 256>>>(mask, out_w);

    // rows = B*NH*S = 131072, 8 warps (rows) per block
    softmax_kernel<<<131072 / 8, 256>>>(out_w);

    dim3 cg(1, S_LEN / 128, B_SZ * NHEAD);   // (1, 8, 128)
    ctx_kernel<<<cg, 256>>>(out_w, out_ctx);
}

// round 5
// speedup vs baseline: 1.2127x; 1.2127x over previous
#include <cuda_runtime.h>
#include <math_constants.h>

// Problem constants
#define S_LEN 1024
#define B_SZ  8
#define H_DIM 1024
#define NHEAD 16
#define HDIM  64
#define M_ROWS (B_SZ * S_LEN)   // 8192

// Scratch for projected Q/K/V, [B*S, H] with m = b*S_LEN + s.
__device__ float g_QL[(size_t)M_ROWS * H_DIM];
__device__ float g_KL[(size_t)M_ROWS * H_DIM];
__device__ float g_VL[(size_t)M_ROWS * H_DIM];

// ---------------------------------------------------------------------------
// Packed fp32x2 helpers (sm_100+): one FFMA2 does 2 fp32 FMAs on the fma pipe.
// ---------------------------------------------------------------------------
__device__ __forceinline__ unsigned long long ffma2(
    unsigned long long a, unsigned long long b, unsigned long long c)
{
    unsigned long long d;
    asm("fma.rn.f32x2 %0, %1, %2, %3;" : "=l"(d) : "l"(a), "l"(b), "l"(c));
    return d;
}
__device__ __forceinline__ unsigned long long pack2(float x)
{
    unsigned long long d;
    asm("mov.b64 %0, {%1, %1};" : "=l"(d) : "f"(x));
    return d;
}
__device__ __forceinline__ void unpack2(unsigned long long v, float& lo, float& hi)
{
    asm("mov.b64 {%0, %1}, %2;" : "=f"(lo), "=f"(hi) : "l"(v));
}

// ---------------------------------------------------------------------------
// Projection GEMM: Y[m][n] = sum_k X[(s*B+b)][k] * W[n][k] + bias[n]
//   128x128 tile, BK=16, 256 threads, 8x8 per thread, f32x2 inner loop.
// ---------------------------------------------------------------------------
__global__ __launch_bounds__(256, 2) void proj_kernel(
    const float* __restrict__ X, const float* __restrict__ W,
    const float* __restrict__ bias, int which)
{
    float* out = (which == 0) ? g_QL : ((which == 1) ? g_KL : g_VL);

    const int BK = 16;
    __shared__ float As[BK][132];
    __shared__ float Bs[BK][132];

    const int m0 = blockIdx.y * 128;
    const int n0 = blockIdx.x * 128;
    const int tid = threadIdx.x;
    const int tx = tid & 15;
    const int ty = tid >> 4;

    unsigned long long acc[8][4];
    #pragma unroll
    for (int i = 0; i < 8; i++)
        #pragma unroll
        for (int j = 0; j < 4; j++) acc[i][j] = 0ull;

    for (int k0 = 0; k0 < H_DIM; k0 += BK) {
        #pragma unroll
        for (int l = 0; l < 2; l++) {
            int f  = l * 256 + tid;
            int r  = f >> 2;
            int c4 = f & 3;
            int m  = m0 + r;
            int b  = m >> 10;
            int s  = m & 1023;
            const float4 v = *reinterpret_cast<const float4*>(
                X + ((size_t)(s * B_SZ + b)) * H_DIM + k0 + c4 * 4);
            As[c4 * 4 + 0][r] = v.x; As[c4 * 4 + 1][r] = v.y;
            As[c4 * 4 + 2][r] = v.z; As[c4 * 4 + 3][r] = v.w;
        }
        #pragma unroll
        for (int l = 0; l < 2; l++) {
            int f  = l * 256 + tid;
            int r  = f >> 2;
            int c4 = f & 3;
            const float4 v = *reinterpret_cast<const float4*>(
                W + (size_t)(n0 + r) * H_DIM + k0 + c4 * 4);
            Bs[c4 * 4 + 0][r] = v.x; Bs[c4 * 4 + 1][r] = v.y;
            Bs[c4 * 4 + 2][r] = v.z; Bs[c4 * 4 + 3][r] = v.w;
        }
        __syncthreads();

        #pragma unroll
        for (int kk = 0; kk < BK; kk++) {
            float4 a0 = *reinterpret_cast<const float4*>(&As[kk][ty * 8]);
            float4 a1 = *reinterpret_cast<const float4*>(&As[kk][ty * 8 + 4]);
            unsigned long long aa[8];
            aa[0] = pack2(a0.x); aa[1] = pack2(a0.y); aa[2] = pack2(a0.z); aa[3] = pack2(a0.w);
            aa[4] = pack2(a1.x); aa[5] = pack2(a1.y); aa[6] = pack2(a1.z); aa[7] = pack2(a1.w);
            const unsigned long long* bp =
                reinterpret_cast<const unsigned long long*>(&Bs[kk][tx * 8]);
            unsigned long long b0 = bp[0], b1 = bp[1], b2 = bp[2], b3 = bp[3];
            #pragma unroll
            for (int i = 0; i < 8; i++) {
                acc[i][0] = ffma2(aa[i], b0, acc[i][0]);
                acc[i][1] = ffma2(aa[i], b1, acc[i][1]);
                acc[i][2] = ffma2(aa[i], b2, acc[i][2]);
                acc[i][3] = ffma2(aa[i], b3, acc[i][3]);
            }
        }
        __syncthreads();
    }

    const float4 bsv0 = *reinterpret_cast<const float4*>(bias + n0 + tx * 8);
    const float4 bsv1 = *reinterpret_cast<const float4*>(bias + n0 + tx * 8 + 4);
    #pragma unroll
    for (int i = 0; i < 8; i++) {
        int m = m0 + ty * 8 + i;
        float lo, hi;
        float4 o0, o1;
        unpack2(acc[i][0], lo, hi); o0.x = lo + bsv0.x; o0.y = hi + bsv0.y;
        unpack2(acc[i][1], lo, hi); o0.z = lo + bsv0.z; o0.w = hi + bsv0.w;
        unpack2(acc[i][2], lo, hi); o1.x = lo + bsv1.x; o1.y = hi + bsv1.y;
        unpack2(acc[i][3], lo, hi); o1.z = lo + bsv1.z; o1.w = hi + bsv1.w;
        float* op = out + (size_t)m * H_DIM + n0 + tx * 8;
        *reinterpret_cast<float4*>(op)     = o0;
        *reinterpret_cast<float4*>(op + 4) = o1;
    }
}

// ---------------------------------------------------------------------------
// Fused attention: per (bh, q-tile of 128):
//   Phase 1: S = QK^T/8 + mask, written raw to W (attn_weights region),
//            online row max/sum tracked in registers.
//   Phase 2: re-read raw S (L2-hot), p = exp(s-m)/l written back (final
//            attn_weights), and ctx += p*V accumulated in the same pass.
// ---------------------------------------------------------------------------
__global__ __launch_bounds__(256, 2) void attn_kernel(
    const int* __restrict__ mask, float* w, float* out_ctx)
{
    const int bh = blockIdx.y;
    const int b = bh >> 4;
    const int h = bh & 15;
    const int q0 = blockIdx.x * 128;
    const float* Qb = g_QL + (size_t)b * S_LEN * H_DIM + h * HDIM;
    const float* Kb = g_KL + (size_t)b * S_LEN * H_DIM + h * HDIM;
    const float* Vb = g_VL + (size_t)b * S_LEN * H_DIM + h * HDIM;
    float* W = w + (size_t)bh * S_LEN * S_LEN;

    __shared__ float As[16][132];
    __shared__ float Bs[16][132];
    __shared__ float sm_m[128];
    __shared__ float sm_il[128];

    const int tid = threadIdx.x;
    const int tx = tid & 15;
    const int ty = tid >> 4;

    float row_m[8], row_l[8];
    #pragma unroll
    for (int i = 0; i < 8; i++) { row_m[i] = -CUDART_INF_F; row_l[i] = 0.0f; }

    // ---------------- Phase 1: scores + online stats ----------------
    for (int kt = 0; kt < 8; kt++) {
        const int n0 = kt * 128;

        unsigned long long acc[8][4];
        #pragma unroll
        for (int i = 0; i < 8; i++)
            #pragma unroll
            for (int j = 0; j < 4; j++) acc[i][j] = 0ull;

        for (int k0 = 0; k0 < HDIM; k0 += 16) {
            #pragma unroll
            for (int l = 0; l < 2; l++) {
                int f = l * 256 + tid;
                int r = f >> 2, c4 = f & 3;
                const float4 v = *reinterpret_cast<const float4*>(
                    Qb + (size_t)(q0 + r) * H_DIM + k0 + c4 * 4);
                As[c4 * 4 + 0][r] = v.x; As[c4 * 4 + 1][r] = v.y;
                As[c4 * 4 + 2][r] = v.z; As[c4 * 4 + 3][r] = v.w;
            }
            #pragma unroll
            for (int l = 0; l < 2; l++) {
                int f = l * 256 + tid;
                int r = f >> 2, c4 = f & 3;
                const float4 v = *reinterpret_cast<const float4*>(
                    Kb + (size_t)(n0 + r) * H_DIM + k0 + c4 * 4);
                Bs[c4 * 4 + 0][r] = v.x; Bs[c4 * 4 + 1][r] = v.y;
                Bs[c4 * 4 + 2][r] = v.z; Bs[c4 * 4 + 3][r] = v.w;
            }
            __syncthreads();

            #pragma unroll
            for (int kk = 0; kk < 16; kk++) {
                float4 a0 = *reinterpret_cast<const float4*>(&As[kk][ty * 8]);
                float4 a1 = *reinterpret_cast<const float4*>(&As[kk][ty * 8 + 4]);
                unsigned long long aa[8];
                aa[0] = pack2(a0.x); aa[1] = pack2(a0.y); aa[2] = pack2(a0.z); aa[3] = pack2(a0.w);
                aa[4] = pack2(a1.x); aa[5] = pack2(a1.y); aa[6] = pack2(a1.z); aa[7] = pack2(a1.w);
                const unsigned long long* bp =
                    reinterpret_cast<const unsigned long long*>(&Bs[kk][tx * 8]);
                unsigned long long b0 = bp[0], b1 = bp[1], b2 = bp[2], b3 = bp[3];
                #pragma unroll
                for (int i = 0; i < 8; i++) {
                    acc[i][0] = ffma2(aa[i], b0, acc[i][0]);
                    acc[i][1] = ffma2(aa[i], b1, acc[i][1]);
                    acc[i][2] = ffma2(aa[i], b2, acc[i][2]);
                    acc[i][3] = ffma2(aa[i], b3, acc[i][3]);
                }
            }
            __syncthreads();
        }

        // scale + mask
        float madd[8];
        #pragma unroll
        for (int j = 0; j < 8; j++) {
            int n = n0 + tx * 8 + j;
            madd[j] = (mask[b * S_LEN + n] != 0) ? -1000000.0f : 0.0f;
        }

        float sacc[8][8];
        #pragma unroll
        for (int i = 0; i < 8; i++) {
            #pragma unroll
            for (int jj = 0; jj < 4; jj++) {
                float lo, hi;
                unpack2(acc[i][jj], lo, hi);
                sacc[i][2 * jj]     = lo * 0.125f + madd[2 * jj];
                sacc[i][2 * jj + 1] = hi * 0.125f + madd[2 * jj + 1];
            }
        }

        // online stats (rows span the 16 tx lanes = half warp) + raw store
        #pragma unroll
        for (int i = 0; i < 8; i++) {
            float tm = sacc[i][0];
            #pragma unroll
            for (int j = 1; j < 8; j++) tm = fmaxf(tm, sacc[i][j]);
            #pragma unroll
            for (int o = 8; o > 0; o >>= 1)
                tm = fmaxf(tm, __shfl_xor_sync(0xffffffffu, tm, o));
            float ts = 0.0f;
            #pragma unroll
            for (int j = 0; j < 8; j++) ts += __expf(sacc[i][j] - tm);
            #pragma unroll
            for (int o = 8; o > 0; o >>= 1)
                ts += __shfl_xor_sync(0xffffffffu, ts, o);

            float mn = fmaxf(row_m[i], tm);
            row_l[i] = row_l[i] * __expf(row_m[i] - mn) + ts * __expf(tm - mn);
            row_m[i] = mn;

            float4 s0 = make_float4(sacc[i][0], sacc[i][1], sacc[i][2], sacc[i][3]);
            float4 s1 = make_float4(sacc[i][4], sacc[i][5], sacc[i][6], sacc[i][7]);
            float* wp = W + (size_t)(q0 + ty * 8 + i) * S_LEN + n0 + tx * 8;
            *reinterpret_cast<float4*>(wp)     = s0;
            *reinterpret_cast<float4*>(wp + 4) = s1;
        }
    }

    if (tx == 0) {
        #pragma unroll
        for (int i = 0; i < 8; i++) {
            sm_m[ty * 8 + i]  = row_m[i];
            sm_il[ty * 8 + i] = 1.0f / row_l[i];
        }
    }
    __syncthreads();

    // ---------------- Phase 2: normalize (write final weights) + P*V ------
    unsigned long long cacc[8][2];
    #pragma unroll
    for (int i = 0; i < 8; i++) { cacc[i][0] = 0ull; cacc[i][1] = 0ull; }

    for (int k0 = 0; k0 < S_LEN; k0 += 16) {
        // load raw score sub-tile, normalize, write back, stage transposed
        #pragma unroll
        for (int l = 0; l < 2; l++) {
            int f = l * 256 + tid;
            int r = f >> 2, c4 = f & 3;
            float* wp = W + (size_t)(q0 + r) * S_LEN + k0 + c4 * 4;
            float4 v = *reinterpret_cast<const float4*>(wp);
            const float mm = sm_m[r];
            const float il = sm_il[r];
            v.x = __expf(v.x - mm) * il;
            v.y = __expf(v.y - mm) * il;
            v.z = __expf(v.z - mm) * il;
            v.w = __expf(v.w - mm) * il;
            *reinterpret_cast<float4*>(wp) = v;
            As[c4 * 4 + 0][r] = v.x; As[c4 * 4 + 1][r] = v.y;
            As[c4 * 4 + 2][r] = v.z; As[c4 * 4 + 3][r] = v.w;
        }
        // V tile: 16 x 64
        {
            int r = tid >> 4, c4 = tid & 15;
            const float4 v = *reinterpret_cast<const float4*>(
                Vb + (size_t)(k0 + r) * H_DIM + c4 * 4);
            *reinterpret_cast<float4*>(&Bs[r][c4 * 4]) = v;
        }
        __syncthreads();

        #pragma unroll
        for (int kk = 0; kk < 16; kk++) {
            float4 a0 = *reinterpret_cast<const float4*>(&As[kk][ty * 8]);
            float4 a1 = *reinterpret_cast<const float4*>(&As[kk][ty * 8 + 4]);
            unsigned long long aa[8];
            aa[0] = pack2(a0.x); aa[1] = pack2(a0.y); aa[2] = pack2(a0.z); aa[3] = pack2(a0.w);
            aa[4] = pack2(a1.x); aa[5] = pack2(a1.y); aa[6] = pack2(a1.z); aa[7] = pack2(a1.w);
            const unsigned long long* bp =
                reinterpret_cast<const unsigned long long*>(&Bs[kk][tx * 4]);
            unsigned long long b0 = bp[0], b1 = bp[1];
            #pragma unroll
            for (int i = 0; i < 8; i++) {
                cacc[i][0] = ffma2(aa[i], b0, cacc[i][0]);
                cacc[i][1] = ffma2(aa[i], b1, cacc[i][1]);
            }
        }
        __syncthreads();
    }

    // write ctx in [S, B, H] layout
    #pragma unroll
    for (int i = 0; i < 8; i++) {
        int s = q0 + ty * 8 + i;
        float lo, hi;
        float4 o;
        unpack2(cacc[i][0], lo, hi); o.x = lo; o.y = hi;
        unpack2(cacc[i][1], lo, hi); o.z = lo; o.w = hi;
        *reinterpret_cast<float4*>(
            out_ctx + ((size_t)s * B_SZ + b) * H_DIM + h * HDIM + tx * 4) = o;
    }
}

// ---------------------------------------------------------------------------
// Launch
// ---------------------------------------------------------------------------
extern "C" void kernel_launch(void* const* d_in, const int* in_sizes, int n_in,
                              void* d_out, int out_size)
{
    const float* q_states = (const float*)d_in[0];
    const float* k_states = (const float*)d_in[1];
    const float* v_states = (const float*)d_in[2];
    const int*   mask     = (const int*)  d_in[3];
    const float* Wq = (const float*)d_in[4];
    const float* bq = (const float*)d_in[5];
    const float* Wk = (const float*)d_in[6];
    const float* bk = (const float*)d_in[7];
    const float* Wv = (const float*)d_in[8];
    const float* bv = (const float*)d_in[9];

    float* out_ctx = (float*)d_out;                           // [S, B, H]
    float* out_w   = out_ctx + (size_t)S_LEN * B_SZ * H_DIM;  // [B, NH, S, S]

    dim3 pg(H_DIM / 128, M_ROWS / 128);      // (8, 64)
    proj_kernel<<<pg, 256>>>(q_states, Wq, bq, 0);
    proj_kernel<<<pg, 256>>>(k_states, Wk, bk, 1);
    proj_kernel<<<pg, 256>>>(v_states, Wv, bv, 2);

    dim3 ag(S_LEN / 128, B_SZ * NHEAD);      // (8, 128)
    attn_kernel<<<ag, 256>>>(mask, out_w, out_ctx);
}